// round 15
// baseline (speedup 1.0000x reference)
#include <cuda_runtime.h>
#include <cuda_fp16.h>
#include <cstdint>

#define NN 100000
#define NE 800000
#define SLOPE 0.2f
#define LN_EPS 1e-5f

typedef unsigned long long ull;

// ---------------- scratch (static device globals; no allocation) ----------------
__device__ __half g_zh[NN * 128];     // GEMM output z [N,2,64] in fp16 (256 B/row)
__device__ float2 g_el[NN];
__device__ float2 g_er[NN];
__device__ float  g_h1[NN * 64];
__device__ int    g_rowptr[NN + 1];
__device__ int    g_cnt[NN];
__device__ int    g_csrc[NE];
__device__ int    g_blksum[128];

// ---------------- CSR build ----------------
__global__ void hist_k(const int* __restrict__ dst) {
    int i = blockIdx.x * 256 + threadIdx.x;
    if (i < NE) atomicAdd(&g_cnt[dst[i]], 1);
}

__global__ void scan_blk_k() {
    __shared__ int sh[256];
    int t = threadIdx.x, b = blockIdx.x;
    int base = b * 1024 + t * 4;
    int v0 = 0, v1 = 0, v2 = 0, v3 = 0;
    if (base + 0 < NN) v0 = g_cnt[base + 0];
    if (base + 1 < NN) v1 = g_cnt[base + 1];
    if (base + 2 < NN) v2 = g_cnt[base + 2];
    if (base + 3 < NN) v3 = g_cnt[base + 3];
    int tsum = v0 + v1 + v2 + v3;
    sh[t] = tsum;
    __syncthreads();
    for (int off = 1; off < 256; off <<= 1) {
        int x = 0;
        if (t >= off) x = sh[t - off];
        __syncthreads();
        sh[t] += x;
        __syncthreads();
    }
    int excl = sh[t] - tsum;
    if (t == 255) g_blksum[b] = sh[255];
    if (base + 0 < NN) g_rowptr[base + 0] = excl;
    if (base + 1 < NN) g_rowptr[base + 1] = excl + v0;
    if (base + 2 < NN) g_rowptr[base + 2] = excl + v0 + v1;
    if (base + 3 < NN) g_rowptr[base + 3] = excl + v0 + v1 + v2;
}

__global__ void scan_top_k(int g) {
    __shared__ int sh[128];
    int t = threadIdx.x;
    int v = (t < g) ? g_blksum[t] : 0;
    sh[t] = v;
    __syncthreads();
    for (int off = 1; off < 128; off <<= 1) {
        int x = 0;
        if (t >= off) x = sh[t - off];
        __syncthreads();
        sh[t] += x;
        __syncthreads();
    }
    if (t < g) g_blksum[t] = sh[t] - v;
}

__global__ void scan_add_k() {
    int i = blockIdx.x * 256 + threadIdx.x;
    if (i < NN) g_rowptr[i] += g_blksum[i >> 10];
    if (i == 0) g_rowptr[NN] = NE;
}

__global__ void scatter_k(const int* __restrict__ src, const int* __restrict__ dst) {
    int i = blockIdx.x * 256 + threadIdx.x;
    if (i < NE) {
        int d = dst[i];
        int p = g_rowptr[d] + atomicAdd(&g_cnt[d], 1);
        g_csrc[p] = src[i];
    }
}

// ---------------- tensor-core GEMM: z = x @ W via mma.sync fp16 hi/lo split ----------------
// D = hiA*hiB + hiA*loB + loA*hiB (fp32 accum). Dropped loA*loB ~2^-22 rel.
// CTA: 128 rows x 128 cols, 8 warps; warp tile 32 rows x 64 cols
//   warp w: rw = w&3 (rows rw*32..), cw = w>>2 (cols cw*64..)
//   2 row-subtiles (m16) x 8 col-subtiles (n8), K chunks of 16.
// smem stride 72 halves (144B) -> conflict-free fragment loads.

__device__ __forceinline__ void mma16816(float* c, const uint32_t* a, uint32_t b0, uint32_t b1) {
    asm volatile(
        "mma.sync.aligned.m16n8k16.row.col.f32.f16.f16.f32 "
        "{%0,%1,%2,%3}, {%4,%5,%6,%7}, {%8,%9}, {%0,%1,%2,%3};"
        : "+f"(c[0]), "+f"(c[1]), "+f"(c[2]), "+f"(c[3])
        : "r"(a[0]), "r"(a[1]), "r"(a[2]), "r"(a[3]), "r"(b0), "r"(b1));
}

#define SSTR 72  // smem stride in halves

template <int FIN>
__global__ void __launch_bounds__(256, 2) gemm_k(const float* __restrict__ x,
                                                 const float* __restrict__ W,
                                                 const float* __restrict__ al,
                                                 const float* __restrict__ ar) {
    extern __shared__ char smc[];
    __half* Ahi = (__half*)smc;            // 128 x SSTR
    __half* Alo = Ahi + 128 * SSTR;
    __half* Bhi = Alo + 128 * SSTR;        // B^T: [n][k] 128 x SSTR
    __half* Blo = Bhi + 128 * SSTR;
    float* Als = (float*)(Blo + 128 * SSTR);  // 128
    float* Ars = Als + 128;

    const int tid = threadIdx.x;
    const int lane = tid & 31, wid = tid >> 5;
    const int g = lane >> 2, t = lane & 3;
    const int rw = wid & 3, cw = wid >> 2;
    const int n0 = blockIdx.x * 128;

    if (tid < 128) { Als[tid] = al[tid]; Ars[tid] = ar[tid]; }

    float acc[2][8][4];
#pragma unroll
    for (int s = 0; s < 2; s++)
#pragma unroll
        for (int j = 0; j < 8; j++)
#pragma unroll
            for (int c = 0; c < 4; c++) acc[s][j][c] = 0.f;

    for (int kt = 0; kt < FIN; kt += 64) {
        // ---- fill A: x rows -> hi/lo fp16, [row][k] stride SSTR ----
        for (int i = tid; i < 2048; i += 256) {
            int r = i >> 4, c4 = i & 15;
            int gr = n0 + r;
            float4 v = make_float4(0.f, 0.f, 0.f, 0.f);
            if (gr < NN) v = *(const float4*)(x + gr * FIN + kt + c4 * 4);
            __half h0 = __float2half_rn(v.x), h1 = __float2half_rn(v.y);
            __half h2 = __float2half_rn(v.z), h3 = __float2half_rn(v.w);
            __half l0 = __float2half_rn(v.x - __half2float(h0));
            __half l1 = __float2half_rn(v.y - __half2float(h1));
            __half l2 = __float2half_rn(v.z - __half2float(h2));
            __half l3 = __float2half_rn(v.w - __half2float(h3));
            __half* pa = Ahi + r * SSTR + c4 * 4;
            pa[0] = h0; pa[1] = h1; pa[2] = h2; pa[3] = h3;
            __half* pb = Alo + r * SSTR + c4 * 4;
            pb[0] = l0; pb[1] = l1; pb[2] = l2; pb[3] = l3;
        }
        // ---- fill B^T: W[kt+k][n] -> [n][k], hi/lo ----
        for (int i = tid; i < 2048; i += 256) {
            int k = i >> 5, n4 = i & 31;
            float4 v = *(const float4*)(W + (kt + k) * 128 + n4 * 4);
#pragma unroll
            for (int e = 0; e < 4; e++) {
                float xv = (&v.x)[e];
                __half hv = __float2half_rn(xv);
                __half lv = __float2half_rn(xv - __half2float(hv));
                int n = n4 * 4 + e;
                Bhi[n * SSTR + k] = hv;
                Blo[n * SSTR + k] = lv;
            }
        }
        __syncthreads();

        // ---- 4 k-chunks of 16 ----
#pragma unroll
        for (int kc = 0; kc < 64; kc += 16) {
            uint32_t ahi[2][4], alo[2][4];
#pragma unroll
            for (int s = 0; s < 2; s++) {
                int r0 = rw * 32 + s * 16;
                const __half* ph = Ahi + kc + t * 2;
                const __half* pl = Alo + kc + t * 2;
                ahi[s][0] = *(const uint32_t*)(ph + (r0 + g) * SSTR);
                ahi[s][1] = *(const uint32_t*)(ph + (r0 + g + 8) * SSTR);
                ahi[s][2] = *(const uint32_t*)(ph + (r0 + g) * SSTR + 8);
                ahi[s][3] = *(const uint32_t*)(ph + (r0 + g + 8) * SSTR + 8);
                alo[s][0] = *(const uint32_t*)(pl + (r0 + g) * SSTR);
                alo[s][1] = *(const uint32_t*)(pl + (r0 + g + 8) * SSTR);
                alo[s][2] = *(const uint32_t*)(pl + (r0 + g) * SSTR + 8);
                alo[s][3] = *(const uint32_t*)(pl + (r0 + g + 8) * SSTR + 8);
            }
#pragma unroll
            for (int j = 0; j < 8; j++) {
                int nb = cw * 64 + j * 8 + g;
                uint32_t bh0 = *(const uint32_t*)(Bhi + nb * SSTR + kc + t * 2);
                uint32_t bh1 = *(const uint32_t*)(Bhi + nb * SSTR + kc + t * 2 + 8);
                uint32_t bl0 = *(const uint32_t*)(Blo + nb * SSTR + kc + t * 2);
                uint32_t bl1 = *(const uint32_t*)(Blo + nb * SSTR + kc + t * 2 + 8);
#pragma unroll
                for (int s = 0; s < 2; s++) {
                    mma16816(acc[s][j], ahi[s], bh0, bh1);
                    mma16816(acc[s][j], ahi[s], bl0, bl1);
                    mma16816(acc[s][j], alo[s], bh0, bh1);
                }
            }
        }
        __syncthreads();
    }

    // ---- epilogue: z fp16 store + el/er (head = cw) ----
    const float* alp = Als + cw * 64;
    const float* arp = Ars + cw * 64;
#pragma unroll
    for (int s = 0; s < 2; s++) {
        int grA = n0 + rw * 32 + s * 16 + g;
        int grB = grA + 8;
        float elA = 0.f, erA = 0.f, elB = 0.f, erB = 0.f;
#pragma unroll
        for (int j = 0; j < 8; j++) {
            int c = j * 8 + t * 2;
            elA += acc[s][j][0] * alp[c] + acc[s][j][1] * alp[c + 1];
            erA += acc[s][j][0] * arp[c] + acc[s][j][1] * arp[c + 1];
            elB += acc[s][j][2] * alp[c] + acc[s][j][3] * alp[c + 1];
            erB += acc[s][j][2] * arp[c] + acc[s][j][3] * arp[c + 1];
            if (grA < NN) {
                __half2 hv = __floats2half2_rn(acc[s][j][0], acc[s][j][1]);
                *(__half2*)(g_zh + grA * 128 + cw * 64 + c) = hv;
            }
            if (grB < NN) {
                __half2 hv = __floats2half2_rn(acc[s][j][2], acc[s][j][3]);
                *(__half2*)(g_zh + grB * 128 + cw * 64 + c) = hv;
            }
        }
        elA += __shfl_xor_sync(0xffffffffu, elA, 1); elA += __shfl_xor_sync(0xffffffffu, elA, 2);
        erA += __shfl_xor_sync(0xffffffffu, erA, 1); erA += __shfl_xor_sync(0xffffffffu, erA, 2);
        elB += __shfl_xor_sync(0xffffffffu, elB, 1); elB += __shfl_xor_sync(0xffffffffu, elB, 2);
        erB += __shfl_xor_sync(0xffffffffu, erB, 1); erB += __shfl_xor_sync(0xffffffffu, erB, 2);
        if (t == 0) {
            if (grA < NN) {
                ((float*)g_el)[grA * 2 + cw] = elA;
                ((float*)g_er)[grA * 2 + cw] = erA;
            }
            if (grB < NN) {
                ((float*)g_el)[grB * 2 + cw] = elB;
                ((float*)g_er)[grB * 2 + cw] = erB;
            }
        }
    }
}

// ---------------- warp-per-node: single-pass softmax + aggregate (fp16 z, unroll 4) ----------------
__device__ __forceinline__ float lrelu(float v) { return v > 0.f ? v : SLOPE * v; }

__device__ __forceinline__ float4 h4_to_f4(uint2 u) {
    float2 lo = __half22float2(*(__half2*)&u.x);
    float2 hi = __half22float2(*(__half2*)&u.y);
    return make_float4(lo.x, lo.y, hi.x, hi.y);
}

template <int LAYER>
__global__ void __launch_bounds__(256) agg_k(const float* __restrict__ bias,
                                             const float* __restrict__ gamma,
                                             const float* __restrict__ beta,
                                             float* __restrict__ outp) {
    int warp = (blockIdx.x * 256 + threadIdx.x) >> 5;
    int lane = threadIdx.x & 31;
    if (warp >= NN) return;
    const int n = warp;
    const int base = g_rowptr[n];
    const int deg = g_rowptr[n + 1] - base;
    const float2 erd = g_er[n];

    const int h = lane >> 4;
    const float erh = h ? erd.y : erd.x;
    float den = 0.f;
    float4 acc = make_float4(0.f, 0.f, 0.f, 0.f);
    const uint2* zp = (const uint2*)g_zh;

    int j = 0;
    for (; j + 4 <= deg; j += 4) {
        int s0 = g_csrc[base + j];
        int s1 = g_csrc[base + j + 1];
        int s2 = g_csrc[base + j + 2];
        int s3 = g_csrc[base + j + 3];
        float2 a0 = g_el[s0];
        float2 a1 = g_el[s1];
        float2 a2 = g_el[s2];
        float2 a3 = g_el[s3];
        uint2 u0 = zp[s0 * 32 + lane];
        uint2 u1 = zp[s1 * 32 + lane];
        uint2 u2 = zp[s2 * 32 + lane];
        uint2 u3 = zp[s3 * 32 + lane];
        float w0 = __expf(lrelu((h ? a0.y : a0.x) + erh));
        float w1 = __expf(lrelu((h ? a1.y : a1.x) + erh));
        float w2 = __expf(lrelu((h ? a2.y : a2.x) + erh));
        float w3 = __expf(lrelu((h ? a3.y : a3.x) + erh));
        den += (w0 + w1) + (w2 + w3);
        float4 v0 = h4_to_f4(u0), v1 = h4_to_f4(u1), v2 = h4_to_f4(u2), v3 = h4_to_f4(u3);
        acc.x = fmaf(w0, v0.x, acc.x); acc.y = fmaf(w0, v0.y, acc.y);
        acc.z = fmaf(w0, v0.z, acc.z); acc.w = fmaf(w0, v0.w, acc.w);
        acc.x = fmaf(w1, v1.x, acc.x); acc.y = fmaf(w1, v1.y, acc.y);
        acc.z = fmaf(w1, v1.z, acc.z); acc.w = fmaf(w1, v1.w, acc.w);
        acc.x = fmaf(w2, v2.x, acc.x); acc.y = fmaf(w2, v2.y, acc.y);
        acc.z = fmaf(w2, v2.z, acc.z); acc.w = fmaf(w2, v2.w, acc.w);
        acc.x = fmaf(w3, v3.x, acc.x); acc.y = fmaf(w3, v3.y, acc.y);
        acc.z = fmaf(w3, v3.z, acc.z); acc.w = fmaf(w3, v3.w, acc.w);
    }
    for (; j < deg; j++) {
        int s = g_csrc[base + j];
        float2 a = g_el[s];
        uint2 u = zp[s * 32 + lane];
        float w = __expf(lrelu((h ? a.y : a.x) + erh));
        den += w;
        float4 v = h4_to_f4(u);
        acc.x = fmaf(w, v.x, acc.x); acc.y = fmaf(w, v.y, acc.y);
        acc.z = fmaf(w, v.z, acc.z); acc.w = fmaf(w, v.w, acc.w);
    }

    const float inv = (deg > 0) ? 1.f / den : 0.f;
    acc.x *= inv; acc.y *= inv; acc.z *= inv; acc.w *= inv;

    float ox = 0.5f * (acc.x + __shfl_xor_sync(0xffffffffu, acc.x, 16));
    float oy = 0.5f * (acc.y + __shfl_xor_sync(0xffffffffu, acc.y, 16));
    float oz = 0.5f * (acc.z + __shfl_xor_sync(0xffffffffu, acc.z, 16));
    float ow = 0.5f * (acc.w + __shfl_xor_sync(0xffffffffu, acc.w, 16));
    const int q = lane & 15;
    float4 bl = ((const float4*)bias)[q];
    float4 bh = ((const float4*)bias)[q + 16];
    ox += 0.5f * (bl.x + bh.x);
    oy += 0.5f * (bl.y + bh.y);
    oz += 0.5f * (bl.z + bh.z);
    ow += 0.5f * (bl.w + bh.w);

    if (LAYER == 1) {
        float lsum = ox + oy + oz + ow;
        float lsq = ox * ox + oy * oy + oz * oz + ow * ow;
#pragma unroll
        for (int o = 16; o; o >>= 1) {
            lsum += __shfl_xor_sync(0xffffffffu, lsum, o);
            lsq  += __shfl_xor_sync(0xffffffffu, lsq, o);
        }
        float mu = lsum * (1.f / 128.f);
        float var = lsq * (1.f / 128.f) - mu * mu;
        float rs = rsqrtf(var + LN_EPS);
        if (lane < 16) {
            float4 g = ((const float4*)gamma)[q];
            float4 be = ((const float4*)beta)[q];
            float y0 = fmaxf((ox - mu) * rs * g.x + be.x, 0.f);
            float y1 = fmaxf((oy - mu) * rs * g.y + be.y, 0.f);
            float y2 = fmaxf((oz - mu) * rs * g.z + be.z, 0.f);
            float y3 = fmaxf((ow - mu) * rs * g.w + be.w, 0.f);
            ((float4*)outp)[n * 16 + q] = make_float4(y0, y1, y2, y3);
        }
    } else {
        if (lane < 16) ((float4*)outp)[n * 16 + q] = make_float4(ox, oy, oz, ow);
    }
}

// ---------------- host ----------------
extern "C" void kernel_launch(void* const* d_in, const int* in_sizes, int n_in,
                              void* d_out, int out_size) {
    const float* feat   = (const float*)d_in[0];
    const int*   src    = (const int*)d_in[1];
    const int*   dst    = (const int*)d_in[2];
    const float* W1     = (const float*)d_in[3];
    const float* al1    = (const float*)d_in[4];
    const float* ar1    = (const float*)d_in[5];
    const float* b1     = (const float*)d_in[6];
    const float* gamma1 = (const float*)d_in[7];
    const float* beta1  = (const float*)d_in[8];
    const float* W2     = (const float*)d_in[9];
    const float* al2    = (const float*)d_in[10];
    const float* ar2    = (const float*)d_in[11];
    const float* b2     = (const float*)d_in[12];
    float* out = (float*)d_out;
    (void)in_sizes; (void)n_in; (void)out_size;

    void* tmp;
    cudaGetSymbolAddress(&tmp, g_cnt);  int* cntp = (int*)tmp;
    cudaGetSymbolAddress(&tmp, g_h1);   float* h1p = (float*)tmp;

    // 4 * 128 * 72 halves + 256 floats = 73728 + 1024 = 74752 B
    const int smem_bytes = 4 * 128 * SSTR * 2 + 256 * 4;
    cudaFuncSetAttribute((const void*)gemm_k<128>,
                         cudaFuncAttributeMaxDynamicSharedMemorySize, smem_bytes);
    cudaFuncSetAttribute((const void*)gemm_k<64>,
                         cudaFuncAttributeMaxDynamicSharedMemorySize, smem_bytes);

    const int ngrid = (NN + 127) / 128;

    // gemm1 kept as overall launch #6 so ncu -s5 -c1 lands on it again.
    cudaMemsetAsync(cntp, 0, NN * sizeof(int));
    hist_k<<<(NE + 255) / 256, 256>>>(dst);
    scan_blk_k<<<(NN + 1023) / 1024, 256>>>();
    scan_top_k<<<1, 128>>>((NN + 1023) / 1024);
    gemm_k<128><<<ngrid, 256, smem_bytes>>>(feat, W1, al1, ar1);
    scan_add_k<<<(NN + 255) / 256, 256>>>();
    cudaMemsetAsync(cntp, 0, NN * sizeof(int));
    scatter_k<<<(NE + 255) / 256, 256>>>(src, dst);

    agg_k<1><<<(NN + 7) / 8, 256>>>(b1, gamma1, beta1, h1p);
    gemm_k<64><<<ngrid, 256, smem_bytes>>>(h1p, W2, al2, ar2);
    agg_k<2><<<(NN + 7) / 8, 256>>>(b2, nullptr, nullptr, out);
}

// round 17
// speedup vs baseline: 1.3078x; 1.3078x over previous
#include <cuda_runtime.h>
#include <cuda_fp16.h>
#include <cstdint>

#define NN 100000
#define NE 800000
#define SLOPE 0.2f
#define LN_EPS 1e-5f

typedef unsigned long long ull;

// ---------------- scratch (static device globals; no allocation) ----------------
__device__ __half g_zh[NN * 128];     // GEMM output z [N,2,64] in fp16 (256 B/row)
__device__ float2 g_el[NN];
__device__ float2 g_er[NN];
__device__ float  g_h1[NN * 64];
__device__ int    g_rowptr[NN + 1];
__device__ int    g_cnt[NN];
__device__ int    g_csrc[NE];
__device__ int    g_blksum[128];

// ---------------- CSR build ----------------
__global__ void hist_k(const int* __restrict__ dst) {
    int i = blockIdx.x * 256 + threadIdx.x;
    if (i < NE) atomicAdd(&g_cnt[dst[i]], 1);
}

__global__ void scan_blk_k() {
    __shared__ int sh[256];
    int t = threadIdx.x, b = blockIdx.x;
    int base = b * 1024 + t * 4;
    int v0 = 0, v1 = 0, v2 = 0, v3 = 0;
    if (base + 0 < NN) v0 = g_cnt[base + 0];
    if (base + 1 < NN) v1 = g_cnt[base + 1];
    if (base + 2 < NN) v2 = g_cnt[base + 2];
    if (base + 3 < NN) v3 = g_cnt[base + 3];
    int tsum = v0 + v1 + v2 + v3;
    sh[t] = tsum;
    __syncthreads();
    for (int off = 1; off < 256; off <<= 1) {
        int x = 0;
        if (t >= off) x = sh[t - off];
        __syncthreads();
        sh[t] += x;
        __syncthreads();
    }
    int excl = sh[t] - tsum;
    if (t == 255) g_blksum[b] = sh[255];
    if (base + 0 < NN) g_rowptr[base + 0] = excl;
    if (base + 1 < NN) g_rowptr[base + 1] = excl + v0;
    if (base + 2 < NN) g_rowptr[base + 2] = excl + v0 + v1;
    if (base + 3 < NN) g_rowptr[base + 3] = excl + v0 + v1 + v2;
}

__global__ void scan_top_k(int g) {
    __shared__ int sh[128];
    int t = threadIdx.x;
    int v = (t < g) ? g_blksum[t] : 0;
    sh[t] = v;
    __syncthreads();
    for (int off = 1; off < 128; off <<= 1) {
        int x = 0;
        if (t >= off) x = sh[t - off];
        __syncthreads();
        sh[t] += x;
        __syncthreads();
    }
    if (t < g) g_blksum[t] = sh[t] - v;
}

__global__ void scan_add_k() {
    int i = blockIdx.x * 256 + threadIdx.x;
    if (i < NN) g_rowptr[i] += g_blksum[i >> 10];
    if (i == 0) g_rowptr[NN] = NE;
}

__global__ void scatter_k(const int* __restrict__ src, const int* __restrict__ dst) {
    int i = blockIdx.x * 256 + threadIdx.x;
    if (i < NE) {
        int d = dst[i];
        int p = g_rowptr[d] + atomicAdd(&g_cnt[d], 1);
        g_csrc[p] = src[i];
    }
}

// ---------------- tensor-core GEMM with ldmatrix + conflict-free layouts ----------------
// D = hiA*hiB + hiA*loB + loA*hiB (fp32 accum), fp16 hi/lo split of both operands.
// A smem: [row][k] stride 72 halves (144B, LDSM-conflict-free).
// B smem: [k][n]  stride 136 halves (272B, LDSM-conflict-free), filled VECTORIZED
//         (no transpose in fill -> no bank-conflict storm), transposed by ldmatrix.trans.
// CTA 128x128, 8 warps, warp tile 32rows x 64cols.

#define SA 72
#define SB 136

__device__ __forceinline__ void mma16816(float* c, const uint32_t* a, uint32_t b0, uint32_t b1) {
    asm volatile(
        "mma.sync.aligned.m16n8k16.row.col.f32.f16.f16.f32 "
        "{%0,%1,%2,%3}, {%4,%5,%6,%7}, {%8,%9}, {%0,%1,%2,%3};"
        : "+f"(c[0]), "+f"(c[1]), "+f"(c[2]), "+f"(c[3])
        : "r"(a[0]), "r"(a[1]), "r"(a[2]), "r"(a[3]), "r"(b0), "r"(b1));
}
__device__ __forceinline__ void ldsm_x4(uint32_t* r, uint32_t addr) {
    asm volatile("ldmatrix.sync.aligned.m8n8.x4.shared.b16 {%0,%1,%2,%3}, [%4];"
                 : "=r"(r[0]), "=r"(r[1]), "=r"(r[2]), "=r"(r[3]) : "r"(addr));
}
__device__ __forceinline__ void ldsm_x4_t(uint32_t* r, uint32_t addr) {
    asm volatile("ldmatrix.sync.aligned.m8n8.x4.trans.shared.b16 {%0,%1,%2,%3}, [%4];"
                 : "=r"(r[0]), "=r"(r[1]), "=r"(r[2]), "=r"(r[3]) : "r"(addr));
}

template <int FIN>
__global__ void __launch_bounds__(256, 2) gemm_k(const float* __restrict__ x,
                                                 const float* __restrict__ W,
                                                 const float* __restrict__ al,
                                                 const float* __restrict__ ar) {
    extern __shared__ char smc[];
    __half* Ahi = (__half*)smc;                // 128 x SA
    __half* Alo = Ahi + 128 * SA;
    __half* Bhi = Alo + 128 * SA;              // 64 x SB, [k][n]
    __half* Blo = Bhi + 64 * SB;
    float* Als = (float*)(Blo + 64 * SB);      // 128
    float* Ars = Als + 128;

    const int tid = threadIdx.x;
    const int lane = tid & 31, wid = tid >> 5;
    const int g = lane >> 2, t = lane & 3;
    const int rw = wid & 3, cw = wid >> 2;
    const int n0 = blockIdx.x * 128;

    if (tid < 128) { Als[tid] = al[tid]; Ars[tid] = ar[tid]; }

    // ldmatrix lane-address components
    const int l8 = lane & 7;                 // row within 8x8 tile
    const int lg1 = (lane >> 3) & 1;         // tile group bit 1
    const int lg2 = lane >> 4;               // tile group bit 2
    const uint32_t AhiB = (uint32_t)__cvta_generic_to_shared(Ahi);
    const uint32_t AloB = (uint32_t)__cvta_generic_to_shared(Alo);
    const uint32_t BhiB = (uint32_t)__cvta_generic_to_shared(Bhi);
    const uint32_t BloB = (uint32_t)__cvta_generic_to_shared(Blo);
    // A tile (r0, kc): row = r0 + l8 + lg1*8, col = kc + lg2*8
    const uint32_t aRow = (uint32_t)(rw * 32 + l8 + lg1 * 8);
    const uint32_t aOffLane = aRow * SA * 2 + (uint32_t)lg2 * 16;
    // B tile (kc, nb): k = kc + l8 + lg1*8, n = nb + lg2*8
    const uint32_t bK = (uint32_t)(l8 + lg1 * 8);
    const uint32_t bOffLane = bK * SB * 2 + (uint32_t)(cw * 64 + lg2 * 8) * 2;

    float acc[2][8][4];
#pragma unroll
    for (int s = 0; s < 2; s++)
#pragma unroll
        for (int j = 0; j < 8; j++)
#pragma unroll
            for (int c = 0; c < 4; c++) acc[s][j][c] = 0.f;

    for (int kt = 0; kt < FIN; kt += 64) {
        // ---- fill A: [row][k] hi/lo, vectorized 8B stores ----
        for (int i = tid; i < 2048; i += 256) {
            int r = i >> 4, c4 = i & 15;
            int gr = n0 + r;
            float4 v = make_float4(0.f, 0.f, 0.f, 0.f);
            if (gr < NN) v = *(const float4*)(x + gr * FIN + kt + c4 * 4);
            __half2 h01 = __floats2half2_rn(v.x, v.y);
            __half2 h23 = __floats2half2_rn(v.z, v.w);
            float2 f01 = __half22float2(h01), f23 = __half22float2(h23);
            __half2 l01 = __floats2half2_rn(v.x - f01.x, v.y - f01.y);
            __half2 l23 = __floats2half2_rn(v.z - f23.x, v.w - f23.y);
            uint2 hv, lv;
            hv.x = *(uint32_t*)&h01; hv.y = *(uint32_t*)&h23;
            lv.x = *(uint32_t*)&l01; lv.y = *(uint32_t*)&l23;
            *(uint2*)(Ahi + r * SA + c4 * 4) = hv;
            *(uint2*)(Alo + r * SA + c4 * 4) = lv;
        }
        // ---- fill B: [k][n] hi/lo, vectorized 8B stores (contiguous per warp) ----
        for (int i = tid; i < 2048; i += 256) {
            int k = i >> 5, n4 = i & 31;
            float4 v = *(const float4*)(W + (kt + k) * 128 + n4 * 4);
            __half2 h01 = __floats2half2_rn(v.x, v.y);
            __half2 h23 = __floats2half2_rn(v.z, v.w);
            float2 f01 = __half22float2(h01), f23 = __half22float2(h23);
            __half2 l01 = __floats2half2_rn(v.x - f01.x, v.y - f01.y);
            __half2 l23 = __floats2half2_rn(v.z - f23.x, v.w - f23.y);
            uint2 hv, lv;
            hv.x = *(uint32_t*)&h01; hv.y = *(uint32_t*)&h23;
            lv.x = *(uint32_t*)&l01; lv.y = *(uint32_t*)&l23;
            *(uint2*)(Bhi + k * SB + n4 * 4) = hv;
            *(uint2*)(Blo + k * SB + n4 * 4) = lv;
        }
        __syncthreads();

#pragma unroll
        for (int kc = 0; kc < 64; kc += 16) {
            uint32_t ahi[2][4], alo[2][4];
#pragma unroll
            for (int s = 0; s < 2; s++) {
                uint32_t ao = aOffLane + (uint32_t)(s * 16) * SA * 2 + (uint32_t)kc * 2;
                ldsm_x4(ahi[s], AhiB + ao);
                ldsm_x4(alo[s], AloB + ao);
            }
#pragma unroll
            for (int jj = 0; jj < 4; jj++) {
                uint32_t bo = bOffLane + (uint32_t)kc * SB * 2 + (uint32_t)(jj * 16) * 2;
                uint32_t bh[4], bl[4];
                ldsm_x4_t(bh, BhiB + bo);
                ldsm_x4_t(bl, BloB + bo);
#pragma unroll
                for (int s = 0; s < 2; s++) {
                    mma16816(acc[s][2 * jj], ahi[s], bh[0], bh[1]);
                    mma16816(acc[s][2 * jj], ahi[s], bl[0], bl[1]);
                    mma16816(acc[s][2 * jj], alo[s], bh[0], bh[1]);
                    mma16816(acc[s][2 * jj + 1], ahi[s], bh[2], bh[3]);
                    mma16816(acc[s][2 * jj + 1], ahi[s], bl[2], bl[3]);
                    mma16816(acc[s][2 * jj + 1], alo[s], bh[2], bh[3]);
                }
            }
        }
        __syncthreads();
    }

    // ---- epilogue: z fp16 store + el/er (head = cw) ----
    const float* alp = Als + cw * 64;
    const float* arp = Ars + cw * 64;
#pragma unroll
    for (int s = 0; s < 2; s++) {
        int grA = n0 + rw * 32 + s * 16 + g;
        int grB = grA + 8;
        float elA = 0.f, erA = 0.f, elB = 0.f, erB = 0.f;
#pragma unroll
        for (int j = 0; j < 8; j++) {
            int c = j * 8 + t * 2;
            elA += acc[s][j][0] * alp[c] + acc[s][j][1] * alp[c + 1];
            erA += acc[s][j][0] * arp[c] + acc[s][j][1] * arp[c + 1];
            elB += acc[s][j][2] * alp[c] + acc[s][j][3] * alp[c + 1];
            erB += acc[s][j][2] * arp[c] + acc[s][j][3] * arp[c + 1];
            if (grA < NN) {
                __half2 hv = __floats2half2_rn(acc[s][j][0], acc[s][j][1]);
                *(__half2*)(g_zh + grA * 128 + cw * 64 + c) = hv;
            }
            if (grB < NN) {
                __half2 hv = __floats2half2_rn(acc[s][j][2], acc[s][j][3]);
                *(__half2*)(g_zh + grB * 128 + cw * 64 + c) = hv;
            }
        }
        elA += __shfl_xor_sync(0xffffffffu, elA, 1); elA += __shfl_xor_sync(0xffffffffu, elA, 2);
        erA += __shfl_xor_sync(0xffffffffu, erA, 1); erA += __shfl_xor_sync(0xffffffffu, erA, 2);
        elB += __shfl_xor_sync(0xffffffffu, elB, 1); elB += __shfl_xor_sync(0xffffffffu, elB, 2);
        erB += __shfl_xor_sync(0xffffffffu, erB, 1); erB += __shfl_xor_sync(0xffffffffu, erB, 2);
        if (t == 0) {
            if (grA < NN) {
                ((float*)g_el)[grA * 2 + cw] = elA;
                ((float*)g_er)[grA * 2 + cw] = erA;
            }
            if (grB < NN) {
                ((float*)g_el)[grB * 2 + cw] = elB;
                ((float*)g_er)[grB * 2 + cw] = erB;
            }
        }
    }
}

// ---------------- warp-per-node: single-pass softmax + aggregate (fp16 z, unroll 4) ----------------
__device__ __forceinline__ float lrelu(float v) { return v > 0.f ? v : SLOPE * v; }

__device__ __forceinline__ float4 h4_to_f4(uint2 u) {
    float2 lo = __half22float2(*(__half2*)&u.x);
    float2 hi = __half22float2(*(__half2*)&u.y);
    return make_float4(lo.x, lo.y, hi.x, hi.y);
}

template <int LAYER>
__global__ void __launch_bounds__(256) agg_k(const float* __restrict__ bias,
                                             const float* __restrict__ gamma,
                                             const float* __restrict__ beta,
                                             float* __restrict__ outp) {
    int warp = (blockIdx.x * 256 + threadIdx.x) >> 5;
    int lane = threadIdx.x & 31;
    if (warp >= NN) return;
    const int n = warp;
    const int base = g_rowptr[n];
    const int deg = g_rowptr[n + 1] - base;
    const float2 erd = g_er[n];

    const int h = lane >> 4;
    const float erh = h ? erd.y : erd.x;
    float den = 0.f;
    float4 acc = make_float4(0.f, 0.f, 0.f, 0.f);
    const uint2* zp = (const uint2*)g_zh;

    int j = 0;
    for (; j + 4 <= deg; j += 4) {
        int s0 = g_csrc[base + j];
        int s1 = g_csrc[base + j + 1];
        int s2 = g_csrc[base + j + 2];
        int s3 = g_csrc[base + j + 3];
        float2 a0 = g_el[s0];
        float2 a1 = g_el[s1];
        float2 a2 = g_el[s2];
        float2 a3 = g_el[s3];
        uint2 u0 = zp[s0 * 32 + lane];
        uint2 u1 = zp[s1 * 32 + lane];
        uint2 u2 = zp[s2 * 32 + lane];
        uint2 u3 = zp[s3 * 32 + lane];
        float w0 = __expf(lrelu((h ? a0.y : a0.x) + erh));
        float w1 = __expf(lrelu((h ? a1.y : a1.x) + erh));
        float w2 = __expf(lrelu((h ? a2.y : a2.x) + erh));
        float w3 = __expf(lrelu((h ? a3.y : a3.x) + erh));
        den += (w0 + w1) + (w2 + w3);
        float4 v0 = h4_to_f4(u0), v1 = h4_to_f4(u1), v2 = h4_to_f4(u2), v3 = h4_to_f4(u3);
        acc.x = fmaf(w0, v0.x, acc.x); acc.y = fmaf(w0, v0.y, acc.y);
        acc.z = fmaf(w0, v0.z, acc.z); acc.w = fmaf(w0, v0.w, acc.w);
        acc.x = fmaf(w1, v1.x, acc.x); acc.y = fmaf(w1, v1.y, acc.y);
        acc.z = fmaf(w1, v1.z, acc.z); acc.w = fmaf(w1, v1.w, acc.w);
        acc.x = fmaf(w2, v2.x, acc.x); acc.y = fmaf(w2, v2.y, acc.y);
        acc.z = fmaf(w2, v2.z, acc.z); acc.w = fmaf(w2, v2.w, acc.w);
        acc.x = fmaf(w3, v3.x, acc.x); acc.y = fmaf(w3, v3.y, acc.y);
        acc.z = fmaf(w3, v3.z, acc.z); acc.w = fmaf(w3, v3.w, acc.w);
    }
    for (; j < deg; j++) {
        int s = g_csrc[base + j];
        float2 a = g_el[s];
        uint2 u = zp[s * 32 + lane];
        float w = __expf(lrelu((h ? a.y : a.x) + erh));
        den += w;
        float4 v = h4_to_f4(u);
        acc.x = fmaf(w, v.x, acc.x); acc.y = fmaf(w, v.y, acc.y);
        acc.z = fmaf(w, v.z, acc.z); acc.w = fmaf(w, v.w, acc.w);
    }

    const float inv = (deg > 0) ? 1.f / den : 0.f;
    acc.x *= inv; acc.y *= inv; acc.z *= inv; acc.w *= inv;

    float ox = 0.5f * (acc.x + __shfl_xor_sync(0xffffffffu, acc.x, 16));
    float oy = 0.5f * (acc.y + __shfl_xor_sync(0xffffffffu, acc.y, 16));
    float oz = 0.5f * (acc.z + __shfl_xor_sync(0xffffffffu, acc.z, 16));
    float ow = 0.5f * (acc.w + __shfl_xor_sync(0xffffffffu, acc.w, 16));
    const int q = lane & 15;
    float4 bl = ((const float4*)bias)[q];
    float4 bh = ((const float4*)bias)[q + 16];
    ox += 0.5f * (bl.x + bh.x);
    oy += 0.5f * (bl.y + bh.y);
    oz += 0.5f * (bl.z + bh.z);
    ow += 0.5f * (bl.w + bh.w);

    if (LAYER == 1) {
        float lsum = ox + oy + oz + ow;
        float lsq = ox * ox + oy * oy + oz * oz + ow * ow;
#pragma unroll
        for (int o = 16; o; o >>= 1) {
            lsum += __shfl_xor_sync(0xffffffffu, lsum, o);
            lsq  += __shfl_xor_sync(0xffffffffu, lsq, o);
        }
        float mu = lsum * (1.f / 128.f);
        float var = lsq * (1.f / 128.f) - mu * mu;
        float rs = rsqrtf(var + LN_EPS);
        if (lane < 16) {
            float4 g = ((const float4*)gamma)[q];
            float4 be = ((const float4*)beta)[q];
            float y0 = fmaxf((ox - mu) * rs * g.x + be.x, 0.f);
            float y1 = fmaxf((oy - mu) * rs * g.y + be.y, 0.f);
            float y2 = fmaxf((oz - mu) * rs * g.z + be.z, 0.f);
            float y3 = fmaxf((ow - mu) * rs * g.w + be.w, 0.f);
            ((float4*)outp)[n * 16 + q] = make_float4(y0, y1, y2, y3);
        }
    } else {
        if (lane < 16) ((float4*)outp)[n * 16 + q] = make_float4(ox, oy, oz, ow);
    }
}

// ---------------- host ----------------
extern "C" void kernel_launch(void* const* d_in, const int* in_sizes, int n_in,
                              void* d_out, int out_size) {
    const float* feat   = (const float*)d_in[0];
    const int*   src    = (const int*)d_in[1];
    const int*   dst    = (const int*)d_in[2];
    const float* W1     = (const float*)d_in[3];
    const float* al1    = (const float*)d_in[4];
    const float* ar1    = (const float*)d_in[5];
    const float* b1     = (const float*)d_in[6];
    const float* gamma1 = (const float*)d_in[7];
    const float* beta1  = (const float*)d_in[8];
    const float* W2     = (const float*)d_in[9];
    const float* al2    = (const float*)d_in[10];
    const float* ar2    = (const float*)d_in[11];
    const float* b2     = (const float*)d_in[12];
    float* out = (float*)d_out;
    (void)in_sizes; (void)n_in; (void)out_size;

    void* tmp;
    cudaGetSymbolAddress(&tmp, g_cnt);  int* cntp = (int*)tmp;
    cudaGetSymbolAddress(&tmp, g_h1);   float* h1p = (float*)tmp;

    // A: 2*128*72*2 = 36864B, B: 2*64*136*2 = 34816B, scales 1024B
    const int smem_bytes = 2 * 128 * SA * 2 + 2 * 64 * SB * 2 + 256 * 4;
    cudaFuncSetAttribute((const void*)gemm_k<128>,
                         cudaFuncAttributeMaxDynamicSharedMemorySize, smem_bytes);
    cudaFuncSetAttribute((const void*)gemm_k<64>,
                         cudaFuncAttributeMaxDynamicSharedMemorySize, smem_bytes);

    const int ngrid = (NN + 127) / 128;

    // gemm1 kept as overall launch #6 so ncu -s5 -c1 lands on it again.
    cudaMemsetAsync(cntp, 0, NN * sizeof(int));
    hist_k<<<(NE + 255) / 256, 256>>>(dst);
    scan_blk_k<<<(NN + 1023) / 1024, 256>>>();
    scan_top_k<<<1, 128>>>((NN + 1023) / 1024);
    gemm_k<128><<<ngrid, 256, smem_bytes>>>(feat, W1, al1, ar1);
    scan_add_k<<<(NN + 255) / 256, 256>>>();
    cudaMemsetAsync(cntp, 0, NN * sizeof(int));
    scatter_k<<<(NE + 255) / 256, 256>>>(src, dst);

    agg_k<1><<<(NN + 7) / 8, 256>>>(b1, gamma1, beta1, h1p);
    gemm_k<64><<<ngrid, 256, smem_bytes>>>(h1p, W2, al2, ar2);
    agg_k<2><<<(NN + 7) / 8, 256>>>(b2, nullptr, nullptr, out);
}